// round 9
// baseline (speedup 1.0000x reference)
#include <cuda_runtime.h>
#include <cuda_bf16.h>
#include <cstdint>

#define BB 4
#define TT 4096
#define CC 1024
#define HS 64
#define SCALE 0.03125f   // CC^-0.5 = 1/32 (reference scales by n_embd, not head_size)

// Scratch for q,k,v projections: [B,T,HS] fp32 each
__device__ float g_q[BB * TT * HS];
__device__ float g_k[BB * TT * HS];
__device__ float g_v[BB * TT * HS];

// ===========================================================================
// mma.sync / ldmatrix helpers (base PTX, legal on plain sm_100)
// ===========================================================================
__device__ __forceinline__ uint32_t smem_u32(const void* p) {
    uint32_t a;
    asm("{ .reg .u64 t; cvta.to.shared.u64 t, %1; cvt.u32.u64 %0, t; }"
        : "=r"(a) : "l"(p));
    return a;
}

__device__ __forceinline__ void ldsm4(uint32_t* r, uint32_t a) {
    asm volatile("ldmatrix.sync.aligned.m8n8.x4.shared.b16 {%0,%1,%2,%3}, [%4];"
        : "=r"(r[0]), "=r"(r[1]), "=r"(r[2]), "=r"(r[3]) : "r"(a));
}
__device__ __forceinline__ void ldsm4t(uint32_t* r, uint32_t a) {
    asm volatile("ldmatrix.sync.aligned.m8n8.x4.trans.shared.b16 {%0,%1,%2,%3}, [%4];"
        : "=r"(r[0]), "=r"(r[1]), "=r"(r[2]), "=r"(r[3]) : "r"(a));
}
// D += A*B, m16n8k16 bf16, fp32 accum (in-place)
__device__ __forceinline__ void mma16816(float* d, const uint32_t* a, const uint32_t* b) {
    asm volatile(
        "mma.sync.aligned.m16n8k16.row.col.f32.bf16.bf16.f32 "
        "{%0,%1,%2,%3}, {%4,%5,%6,%7}, {%8,%9}, {%0,%1,%2,%3};"
        : "+f"(d[0]), "+f"(d[1]), "+f"(d[2]), "+f"(d[3])
        : "r"(a[0]), "r"(a[1]), "r"(a[2]), "r"(a[3]), "r"(b[0]), "r"(b[1]));
}

__device__ __forceinline__ uint32_t pk2(float x, float y) {
    __nv_bfloat162 t = __floats2bfloat162_rn(x, y);
    return *reinterpret_cast<uint32_t*>(&t);
}
__device__ __forceinline__ float bhi(float x) {
    return __bfloat162float(__float2bfloat16_rn(x));
}

// All bf16 tiles: row-major, 64 cols = 128B rows, 16B chunks swizzled chunk^=(row&7)
// A-operand x4 (non-trans)
__device__ __forceinline__ uint32_t a_addr(uint32_t base, int lane, int mbase, int cbase) {
    int t = lane >> 3, r = lane & 7;
    int row = mbase + ((t & 1) << 3) + r;
    int chunk = cbase + (t >> 1);
    return base + row * 128 + (((chunk ^ (row & 7))) << 4);
}
// B from K-style storage [n][k] (non-trans): 2 n-tiles x k16
__device__ __forceinline__ uint32_t bk_addr(uint32_t base, int lane, int nbase, int cbase) {
    int t = lane >> 3, r = lane & 7;
    int row = nbase + ((t >> 1) << 3) + r;
    int chunk = cbase + (t & 1);
    return base + row * 128 + (((chunk ^ (row & 7))) << 4);
}
// B from V-style storage [k][n] (.trans): k32 x one 8-col chunk
__device__ __forceinline__ uint32_t bv_addr(uint32_t base, int lane, int krow0, int chunk) {
    int t = lane >> 3, r = lane & 7;
    int row = krow0 + ((t >> 1) << 4) + ((t & 1) << 3) + r;
    return base + row * 128 + (((chunk ^ (row & 7))) << 4);
}
// B from W-style storage [k][n] (.trans): fixed k16, 2 n-tiles
__device__ __forceinline__ uint32_t bw_addr(uint32_t base, int lane, int krow0, int ntchunk0) {
    int t = lane >> 3, r = lane & 7;
    int row = krow0 + ((t & 1) << 3) + r;
    int chunk = ntchunk0 + (t >> 1);
    return base + row * 128 + (((chunk ^ (row & 7))) << 4);
}

// split fp32 float4 -> hi/lo bf16x4 (8B each) and store at swizzled offset
__device__ __forceinline__ void split_store(char* hi_b, char* lo_b, int row, int q4, float4 v) {
    uint32_t off = (uint32_t)(row * 128 + ((((q4 >> 1) ^ (row & 7))) << 4) + ((q4 & 1) << 3));
    uint2 h, l;
    h.x = pk2(v.x, v.y); h.y = pk2(v.z, v.w);
    l.x = pk2(v.x - bhi(v.x), v.y - bhi(v.y));
    l.y = pk2(v.z - bhi(v.z), v.w - bhi(v.w));
    *(uint2*)(hi_b + off) = h;
    *(uint2*)(lo_b + off) = l;
}

// ===========================================================================
// Kernel 1: QKV projection, mma.sync bf16 3-product.
// CTA: M=128 rows, N=192, K=1024 in 16 stages of 64 -> 128 CTAs = 1 wave.
// x prefetched into registers (DRAM latency); W streamed LDG->STS (L2-hot).
// Warp w owns rows 16w..16w+15, all 192 cols (acc[24][4]).
// ===========================================================================
// per-stage: XHI 0 (16K), XLO 16384 (16K), WHI 32768 (3x8K), WLO 57344 (3x8K)
#define QKV_STAGE 81920
#define QKV_SMEM_BYTES (2 * QKV_STAGE + 768)

__global__ __launch_bounds__(256) void qkv_mma(
    const float* __restrict__ x,
    const float* __restrict__ Wq, const float* __restrict__ bq,
    const float* __restrict__ Wk, const float* __restrict__ bk,
    const float* __restrict__ Wv, const float* __restrict__ bv)
{
    extern __shared__ char sm[];
    float* bias_s = (float*)(sm + 2 * QKV_STAGE);

    const uint32_t sm_u = smem_u32(sm);
    const int tid  = threadIdx.x;
    const int wid  = tid >> 5;
    const int lane = tid & 31;
    const int tg   = lane & 3;
    const int g    = lane >> 2;
    const int m0   = blockIdx.x * 128;
    const int wm   = 16 * wid;
    const int xrow = tid >> 4, xq4 = tid & 15;

    if (tid < 192) {
        const float* bp = (tid < 64) ? bq : ((tid < 128) ? bk : bv);
        bias_s[tid] = bp[tid & 63];
    }

    // prefetch x stage 0 into regs (8 float4: rows xrow + i*16)
    float4 xr[8];
    #pragma unroll
    for (int i = 0; i < 8; i++)
        xr[i] = *(const float4*)(x + (size_t)(m0 + xrow + i * 16) * CC + xq4 * 4);

    float acc[24][4];
    #pragma unroll
    for (int i = 0; i < 24; i++)
        #pragma unroll
        for (int c = 0; c < 4; c++) acc[i][c] = 0.f;

    for (int kb = 0; kb < 16; kb++) {
        const int st = kb & 1;
        char* base = sm + st * QKV_STAGE;
        const uint32_t base_u = sm_u + st * QKV_STAGE;
        const int k0 = kb * 64;

        // store prefetched x regs
        #pragma unroll
        for (int i = 0; i < 8; i++)
            split_store(base, base + 16384, xrow + i * 16, xq4, xr[i]);
        // stream W LDG->split->STS (L2-hot after first CTA touches it)
        #pragma unroll
        for (int ws = 0; ws < 3; ws++) {
            const float* Wp = (ws == 0) ? Wq : ((ws == 1) ? Wk : Wv);
            #pragma unroll
            for (int i = 0; i < 4; i++) {
                int f = tid + i * 256;
                int kr = f >> 4, q4 = f & 15;
                float4 v = *(const float4*)(Wp + (size_t)(k0 + kr) * HS + q4 * 4);
                split_store(base + 32768 + ws * 8192, base + 57344 + ws * 8192, kr, q4, v);
            }
        }
        __syncthreads();

        // prefetch next x stage (overlaps the mma below)
        if (kb < 15) {
            const int k1 = (kb + 1) * 64;
            #pragma unroll
            for (int i = 0; i < 8; i++)
                xr[i] = *(const float4*)(x + (size_t)(m0 + xrow + i * 16) * CC + k1 + xq4 * 4);
        }

        const uint32_t xhi_u = base_u, xlo_u = base_u + 16384;
        const uint32_t whi_u = base_u + 32768, wlo_u = base_u + 57344;
        #pragma unroll
        for (int kc = 0; kc < 4; kc++) {
            uint32_t ah[4], al4[4];
            ldsm4(ah,  a_addr(xhi_u, lane, wm, kc * 2));
            ldsm4(al4, a_addr(xlo_u, lane, wm, kc * 2));
            #pragma unroll
            for (int p = 0; p < 12; p++) {
                int gnt  = 2 * p;
                int wsel = gnt >> 3;
                int lnt  = gnt & 7;
                uint32_t bh[4], bl[4];
                ldsm4t(bh, bw_addr(whi_u + wsel * 8192, lane, kc * 16, lnt));
                ldsm4t(bl, bw_addr(wlo_u + wsel * 8192, lane, kc * 16, lnt));
                #pragma unroll
                for (int i = 0; i < 2; i++) {
                    int ln = gnt + i;
                    mma16816(acc[ln], ah,  &bh[2 * i]);
                    mma16816(acc[ln], ah,  &bl[2 * i]);
                    mma16816(acc[ln], al4, &bh[2 * i]);
                }
            }
        }
        // no trailing sync: next iteration writes the OTHER stage, and its
        // sync proves every warp finished this stage's mma before reuse.
    }

    #pragma unroll
    for (int nt = 0; nt < 24; nt++) {
        int wsel = nt >> 3;
        int col  = (nt & 7) * 8 + 2 * tg;
        float* op = (wsel == 0) ? g_q : ((wsel == 1) ? g_k : g_v);
        float b0 = bias_s[wsel * 64 + col];
        float b1 = bias_s[wsel * 64 + col + 1];
        float2 o0 = make_float2(acc[nt][0] + b0, acc[nt][1] + b1);
        float2 o1 = make_float2(acc[nt][2] + b0, acc[nt][3] + b1);
        *(float2*)(op + (size_t)(m0 + wm + g)     * HS + col) = o0;
        *(float2*)(op + (size_t)(m0 + wm + g + 8) * HS + col) = o1;
    }
}

// ===========================================================================
// Kernel 2: flash attention, warp-specialized, 2 CTAs/SM.
// Warps 0-3: compute (16 rows x 64 cols each; fragment-resident softmax;
//            Q frags re-ldmatrix'd per key tile to fit 128 regs).
// Warps 4-7: producers (double-buffered K/V load+split).
// ===========================================================================
// smem: Qhi 0, Qlo 8192; buf s at 16384+s*32768: Khi+0 Klo+8192 Vhi+16384 Vlo+24576
#define ATTN_SMEM_BYTES (16384 + 2 * 32768)

__global__ __launch_bounds__(256, 2) void attn_mma(float* __restrict__ out)
{
    extern __shared__ char sm[];
    const uint32_t sm_u = smem_u32(sm);

    const int tid  = threadIdx.x;
    const int wid  = tid >> 5;
    const int lane = tid & 31;
    const int g    = lane >> 2;
    const int tg   = lane & 3;
    const bool consumer = (wid < 4);
    const int wm   = 16 * wid;          // consumer row base (wid 0..3)
    const int ptid = tid & 127;         // producer-local tid

    const int b    = blockIdx.y;
    const int pair = blockIdx.x;        // 0..31

    const float* qb = g_q + (size_t)b * TT * HS;
    const float* kb = g_k + (size_t)b * TT * HS;
    const float* vb = g_v + (size_t)b * TT * HS;
    float*       ob = out + (size_t)b * TT * HS;

    for (int half = 0; half < 2; half++) {
        const int qtile = half ? (TT / 64 - 1 - pair) : pair;
        const int m0 = qtile * 64;

        __syncthreads();   // all reads of Q/K/V buffers from previous half done

        if (consumer) {
            // consumers load Q tile (128 threads, 8 float4 each)
            #pragma unroll
            for (int i = 0; i < 8; i++) {
                int f = ptid + i * 128;
                int row = f >> 4, q4 = f & 15;
                float4 v = *(const float4*)(qb + (size_t)(m0 + row) * HS + q4 * 4);
                split_store(sm, sm + 8192, row, q4, v);
            }
        } else {
            // producers prefill buf 0 with K/V tile j=0
            char* kbase = sm + 16384;
            #pragma unroll
            for (int i = 0; i < 8; i++) {
                int f = ptid + i * 128;
                int row = f >> 4, q4 = f & 15;
                float4 kv4 = *(const float4*)(kb + (size_t)row * HS + q4 * 4);
                float4 vv4 = *(const float4*)(vb + (size_t)row * HS + q4 * 4);
                split_store(kbase,         kbase + 8192,  row, q4, kv4);
                split_store(kbase + 16384, kbase + 24576, row, q4, vv4);
            }
        }
        __syncthreads();

        float o[8][4];
        float mr0 = -1e30f, mr1 = -1e30f, lr0 = 0.f, lr1 = 0.f;
        if (consumer) {
            #pragma unroll
            for (int ct = 0; ct < 8; ct++)
                #pragma unroll
                for (int c = 0; c < 4; c++) o[ct][c] = 0.f;
        }

        for (int j = 0; j <= qtile; j++) {
            const int s = j & 1;

            if (!consumer) {
                if (j < qtile) {
                    const int n0n = (j + 1) * 64;
                    char* kbase = sm + 16384 + ((j + 1) & 1) * 32768;
                    #pragma unroll
                    for (int i = 0; i < 8; i++) {
                        int f = ptid + i * 128;
                        int row = f >> 4, q4 = f & 15;
                        float4 kv4 = *(const float4*)(kb + (size_t)(n0n + row) * HS + q4 * 4);
                        float4 vv4 = *(const float4*)(vb + (size_t)(n0n + row) * HS + q4 * 4);
                        split_store(kbase,         kbase + 8192,  row, q4, kv4);
                        split_store(kbase + 16384, kbase + 24576, row, q4, vv4);
                    }
                }
            } else {
                const uint32_t kbu = sm_u + 16384 + s * 32768;
                const uint32_t Khi_u = kbu, Klo_u = kbu + 8192;
                const uint32_t Vhi_u = kbu + 16384, Vlo_u = kbu + 24576;

                // ---- S = Q K^T : 16 rows x 64 cols per warp ----
                float sa[8][4];
                #pragma unroll
                for (int nt = 0; nt < 8; nt++)
                    #pragma unroll
                    for (int c = 0; c < 4; c++) sa[nt][c] = 0.f;

                #pragma unroll
                for (int kc = 0; kc < 4; kc++) {
                    uint32_t qh[4], ql[4];
                    ldsm4(qh, a_addr(sm_u,        lane, wm, kc * 2));
                    ldsm4(ql, a_addr(sm_u + 8192, lane, wm, kc * 2));
                    #pragma unroll
                    for (int ntp = 0; ntp < 4; ntp++) {
                        uint32_t kh[4], kl4[4];
                        ldsm4(kh,  bk_addr(Khi_u, lane, 16 * ntp, kc * 2));
                        ldsm4(kl4, bk_addr(Klo_u, lane, 16 * ntp, kc * 2));
                        #pragma unroll
                        for (int i = 0; i < 2; i++) {
                            int nt = 2 * ntp + i;
                            mma16816(sa[nt], qh, &kh[2 * i]);
                            mma16816(sa[nt], qh, &kl4[2 * i]);
                            mma16816(sa[nt], ql, &kh[2 * i]);
                        }
                    }
                }

                // ---- scale + causal mask ----
                if (j == qtile) {
                    #pragma unroll
                    for (int nt = 0; nt < 8; nt++) {
                        int c0 = nt * 8 + 2 * tg;
                        sa[nt][0] = (c0     <= wm + g)     ? sa[nt][0] * SCALE : -1e30f;
                        sa[nt][1] = (c0 + 1 <= wm + g)     ? sa[nt][1] * SCALE : -1e30f;
                        sa[nt][2] = (c0     <= wm + g + 8) ? sa[nt][2] * SCALE : -1e30f;
                        sa[nt][3] = (c0 + 1 <= wm + g + 8) ? sa[nt][3] * SCALE : -1e30f;
                    }
                } else {
                    #pragma unroll
                    for (int nt = 0; nt < 8; nt++)
                        #pragma unroll
                        for (int c = 0; c < 4; c++) sa[nt][c] *= SCALE;
                }

                // ---- fragment-resident online softmax ----
                float tm0 = -1e30f, tm1 = -1e30f;
                #pragma unroll
                for (int nt = 0; nt < 8; nt++) {
                    tm0 = fmaxf(tm0, fmaxf(sa[nt][0], sa[nt][1]));
                    tm1 = fmaxf(tm1, fmaxf(sa[nt][2], sa[nt][3]));
                }
                tm0 = fmaxf(tm0, __shfl_xor_sync(0xffffffffu, tm0, 1));
                tm0 = fmaxf(tm0, __shfl_xor_sync(0xffffffffu, tm0, 2));
                tm1 = fmaxf(tm1, __shfl_xor_sync(0xffffffffu, tm1, 1));
                tm1 = fmaxf(tm1, __shfl_xor_sync(0xffffffffu, tm1, 2));
                float mn0 = fmaxf(mr0, tm0), mn1 = fmaxf(mr1, tm1);
                float al0 = __expf(mr0 - mn0), al1 = __expf(mr1 - mn1);
                mr0 = mn0; mr1 = mn1;
                float rs0 = 0.f, rs1 = 0.f;
                #pragma unroll
                for (int nt = 0; nt < 8; nt++) {
                    sa[nt][0] = __expf(sa[nt][0] - mn0);
                    sa[nt][1] = __expf(sa[nt][1] - mn0);
                    sa[nt][2] = __expf(sa[nt][2] - mn1);
                    sa[nt][3] = __expf(sa[nt][3] - mn1);
                    rs0 += sa[nt][0] + sa[nt][1];
                    rs1 += sa[nt][2] + sa[nt][3];
                }
                rs0 += __shfl_xor_sync(0xffffffffu, rs0, 1);
                rs0 += __shfl_xor_sync(0xffffffffu, rs0, 2);
                rs1 += __shfl_xor_sync(0xffffffffu, rs1, 1);
                rs1 += __shfl_xor_sync(0xffffffffu, rs1, 2);
                lr0 = lr0 * al0 + rs0;
                lr1 = lr1 * al1 + rs1;
                #pragma unroll
                for (int ct = 0; ct < 8; ct++) {
                    o[ct][0] *= al0; o[ct][1] *= al0;
                    o[ct][2] *= al1; o[ct][3] *= al1;
                }

                // ---- O += P V ; P repacked accum->A-frags in registers ----
                #pragma unroll
                for (int kp = 0; kp < 2; kp++) {      // 32-key groups
                    uint32_t ph[2][4], pl[2][4];
                    #pragma unroll
                    for (int i = 0; i < 2; i++) {     // k16 halves
                        int t0 = 4 * kp + 2 * i;
                        ph[i][0] = pk2(sa[t0][0], sa[t0][1]);
                        ph[i][1] = pk2(sa[t0][2], sa[t0][3]);
                        ph[i][2] = pk2(sa[t0 + 1][0], sa[t0 + 1][1]);
                        ph[i][3] = pk2(sa[t0 + 1][2], sa[t0 + 1][3]);
                        pl[i][0] = pk2(sa[t0][0] - bhi(sa[t0][0]), sa[t0][1] - bhi(sa[t0][1]));
                        pl[i][1] = pk2(sa[t0][2] - bhi(sa[t0][2]), sa[t0][3] - bhi(sa[t0][3]));
                        pl[i][2] = pk2(sa[t0 + 1][0] - bhi(sa[t0 + 1][0]), sa[t0 + 1][1] - bhi(sa[t0 + 1][1]));
                        pl[i][3] = pk2(sa[t0 + 1][2] - bhi(sa[t0 + 1][2]), sa[t0 + 1][3] - bhi(sa[t0 + 1][3]));
                    }
                    #pragma unroll
                    for (int ct = 0; ct < 8; ct++) {
                        uint32_t vh[4], vl[4];
                        ldsm4t(vh, bv_addr(Vhi_u, lane, kp * 32, ct));
                        ldsm4t(vl, bv_addr(Vlo_u, lane, kp * 32, ct));
                        #pragma unroll
                        for (int i = 0; i < 2; i++) {
                            mma16816(o[ct], ph[i], &vh[2 * i]);
                            mma16816(o[ct], ph[i], &vl[2 * i]);
                            mma16816(o[ct], pl[i], &vh[2 * i]);
                        }
                    }
                }
            }
            __syncthreads();
        }

        // ---- epilogue ----
        if (consumer) {
            float inv0 = 1.0f / lr0, inv1 = 1.0f / lr1;
            #pragma unroll
            for (int ct = 0; ct < 8; ct++) {
                int col = ct * 8 + 2 * tg;
                float2 o0 = make_float2(o[ct][0] * inv0, o[ct][1] * inv0);
                float2 o1 = make_float2(o[ct][2] * inv1, o[ct][3] * inv1);
                *(float2*)(ob + (size_t)(m0 + wm + g)     * HS + col) = o0;
                *(float2*)(ob + (size_t)(m0 + wm + g + 8) * HS + col) = o1;
            }
        }
    }
}

// ---------------------------------------------------------------------------
extern "C" void kernel_launch(void* const* d_in, const int* in_sizes, int n_in,
                              void* d_out, int out_size)
{
    const float* x  = (const float*)d_in[0];
    const float* Wq = (const float*)d_in[1];
    const float* bq = (const float*)d_in[2];
    const float* Wk = (const float*)d_in[3];
    const float* bk = (const float*)d_in[4];
    const float* Wv = (const float*)d_in[5];
    const float* bv = (const float*)d_in[6];
    float* out = (float*)d_out;

    (void)cudaFuncSetAttribute(qkv_mma,
                               cudaFuncAttributeMaxDynamicSharedMemorySize,
                               QKV_SMEM_BYTES);
    (void)cudaFuncSetAttribute(attn_mma,
                               cudaFuncAttributeMaxDynamicSharedMemorySize,
                               ATTN_SMEM_BYTES);

    qkv_mma<<<(BB * TT) / 128, 256, QKV_SMEM_BYTES>>>(x, Wq, bq, Wk, bk, Wv, bv);
    attn_mma<<<dim3(TT / 64 / 2, BB), 256, ATTN_SMEM_BYTES>>>(out);
}

// round 10
// speedup vs baseline: 1.0578x; 1.0578x over previous
#include <cuda_runtime.h>
#include <cuda_bf16.h>
#include <cstdint>

#define BB 4
#define TT 4096
#define CC 1024
#define HS 64
#define SCALE 0.03125f   // CC^-0.5 = 1/32 (reference scales by n_embd, not head_size)

// Scratch for q,k,v projections: [B,T,HS] fp32 each
__device__ float g_q[BB * TT * HS];
__device__ float g_k[BB * TT * HS];
__device__ float g_v[BB * TT * HS];

// ===========================================================================
// mma.sync / ldmatrix helpers (base PTX, legal on plain sm_100)
// ===========================================================================
__device__ __forceinline__ uint32_t smem_u32(const void* p) {
    uint32_t a;
    asm("{ .reg .u64 t; cvta.to.shared.u64 t, %1; cvt.u32.u64 %0, t; }"
        : "=r"(a) : "l"(p));
    return a;
}

__device__ __forceinline__ void ldsm4(uint32_t* r, uint32_t a) {
    asm volatile("ldmatrix.sync.aligned.m8n8.x4.shared.b16 {%0,%1,%2,%3}, [%4];"
        : "=r"(r[0]), "=r"(r[1]), "=r"(r[2]), "=r"(r[3]) : "r"(a));
}
__device__ __forceinline__ void ldsm4t(uint32_t* r, uint32_t a) {
    asm volatile("ldmatrix.sync.aligned.m8n8.x4.trans.shared.b16 {%0,%1,%2,%3}, [%4];"
        : "=r"(r[0]), "=r"(r[1]), "=r"(r[2]), "=r"(r[3]) : "r"(a));
}
// D += A*B, m16n8k16 bf16, fp32 accum (in-place)
__device__ __forceinline__ void mma16816(float* d, const uint32_t* a, const uint32_t* b) {
    asm volatile(
        "mma.sync.aligned.m16n8k16.row.col.f32.bf16.bf16.f32 "
        "{%0,%1,%2,%3}, {%4,%5,%6,%7}, {%8,%9}, {%0,%1,%2,%3};"
        : "+f"(d[0]), "+f"(d[1]), "+f"(d[2]), "+f"(d[3])
        : "r"(a[0]), "r"(a[1]), "r"(a[2]), "r"(a[3]), "r"(b[0]), "r"(b[1]));
}

__device__ __forceinline__ uint32_t pk2(float x, float y) {
    __nv_bfloat162 t = __floats2bfloat162_rn(x, y);
    return *reinterpret_cast<uint32_t*>(&t);
}
__device__ __forceinline__ float bhi(float x) {
    return __bfloat162float(__float2bfloat16_rn(x));
}

// All bf16 tiles: row-major, 64 cols = 128B rows, 16B chunks swizzled chunk^=(row&7)
// A-operand x4 (non-trans)
__device__ __forceinline__ uint32_t a_addr(uint32_t base, int lane, int mbase, int cbase) {
    int t = lane >> 3, r = lane & 7;
    int row = mbase + ((t & 1) << 3) + r;
    int chunk = cbase + (t >> 1);
    return base + row * 128 + (((chunk ^ (row & 7))) << 4);
}
// B from K-style storage [n][k] (non-trans): 2 n-tiles x k16
__device__ __forceinline__ uint32_t bk_addr(uint32_t base, int lane, int nbase, int cbase) {
    int t = lane >> 3, r = lane & 7;
    int row = nbase + ((t >> 1) << 3) + r;
    int chunk = cbase + (t & 1);
    return base + row * 128 + (((chunk ^ (row & 7))) << 4);
}
// B from V-style storage [k][n] (.trans): k32 x one 8-col chunk
__device__ __forceinline__ uint32_t bv_addr(uint32_t base, int lane, int krow0, int chunk) {
    int t = lane >> 3, r = lane & 7;
    int row = krow0 + ((t >> 1) << 4) + ((t & 1) << 3) + r;
    return base + row * 128 + (((chunk ^ (row & 7))) << 4);
}
// B from W-style storage [k][n] (.trans): fixed k16, 2 n-tiles
__device__ __forceinline__ uint32_t bw_addr(uint32_t base, int lane, int krow0, int ntchunk0) {
    int t = lane >> 3, r = lane & 7;
    int row = krow0 + ((t & 1) << 3) + r;
    int chunk = ntchunk0 + (t >> 1);
    return base + row * 128 + (((chunk ^ (row & 7))) << 4);
}

// split fp32 float4 -> hi/lo bf16x4 (8B each) and store at swizzled offset
__device__ __forceinline__ void split_store(char* hi_b, char* lo_b, int row, int q4, float4 v) {
    uint32_t off = (uint32_t)(row * 128 + ((((q4 >> 1) ^ (row & 7))) << 4) + ((q4 & 1) << 3));
    uint2 h, l;
    h.x = pk2(v.x, v.y); h.y = pk2(v.z, v.w);
    l.x = pk2(v.x - bhi(v.x), v.y - bhi(v.y));
    l.y = pk2(v.z - bhi(v.z), v.w - bhi(v.w));
    *(uint2*)(hi_b + off) = h;
    *(uint2*)(lo_b + off) = l;
}

// ===========================================================================
// Kernel 1: QKV projection, mma.sync bf16 3-product.
// CTA: M=128 rows, N=192, K=1024 in 16 stages of 64 -> 128 CTAs = 1 wave.
// BOTH x and W prefetched into registers each stage (LDG hoisted after the
// barrier, overlapped with the stage's mma work).
// Warp w owns rows 16w..16w+15, all 192 cols (acc[24][4]).
// ===========================================================================
// per-stage: XHI 0 (16K), XLO 16384 (16K), WHI 32768 (3x8K), WLO 57344 (3x8K)
#define QKV_STAGE 81920
#define QKV_SMEM_BYTES (2 * QKV_STAGE + 768)

__global__ __launch_bounds__(256) void qkv_mma(
    const float* __restrict__ x,
    const float* __restrict__ Wq, const float* __restrict__ bq,
    const float* __restrict__ Wk, const float* __restrict__ bk,
    const float* __restrict__ Wv, const float* __restrict__ bv)
{
    extern __shared__ char sm[];
    float* bias_s = (float*)(sm + 2 * QKV_STAGE);

    const uint32_t sm_u = smem_u32(sm);
    const int tid  = threadIdx.x;
    const int wid  = tid >> 5;
    const int lane = tid & 31;
    const int tg   = lane & 3;
    const int g    = lane >> 2;
    const int m0   = blockIdx.x * 128;
    const int wm   = 16 * wid;
    const int xrow = tid >> 4, xq4 = tid & 15;

    if (tid < 192) {
        const float* bp = (tid < 64) ? bq : ((tid < 128) ? bk : bv);
        bias_s[tid] = bp[tid & 63];
    }

    // prefetch stage 0 into regs: x (8 float4) and W (3 x 4 float4)
    float4 xr[8];
    float4 wr[3][4];
    #pragma unroll
    for (int i = 0; i < 8; i++)
        xr[i] = *(const float4*)(x + (size_t)(m0 + xrow + i * 16) * CC + xq4 * 4);
    #pragma unroll
    for (int ws = 0; ws < 3; ws++) {
        const float* Wp = (ws == 0) ? Wq : ((ws == 1) ? Wk : Wv);
        #pragma unroll
        for (int i = 0; i < 4; i++)
            wr[ws][i] = *(const float4*)(Wp + (size_t)(xrow + i * 16) * HS + xq4 * 4);
    }

    float acc[24][4];
    #pragma unroll
    for (int i = 0; i < 24; i++)
        #pragma unroll
        for (int c = 0; c < 4; c++) acc[i][c] = 0.f;

    for (int kb = 0; kb < 16; kb++) {
        const int st = kb & 1;
        char* base = sm + st * QKV_STAGE;
        const uint32_t base_u = sm_u + st * QKV_STAGE;

        // store prefetched regs -> smem (split bf16)
        #pragma unroll
        for (int i = 0; i < 8; i++)
            split_store(base, base + 16384, xrow + i * 16, xq4, xr[i]);
        #pragma unroll
        for (int ws = 0; ws < 3; ws++)
            #pragma unroll
            for (int i = 0; i < 4; i++)
                split_store(base + 32768 + ws * 8192, base + 57344 + ws * 8192,
                            xrow + i * 16, xq4, wr[ws][i]);
        __syncthreads();

        // prefetch next stage (overlaps the mma below)
        if (kb < 15) {
            const int k1 = (kb + 1) * 64;
            #pragma unroll
            for (int i = 0; i < 8; i++)
                xr[i] = *(const float4*)(x + (size_t)(m0 + xrow + i * 16) * CC + k1 + xq4 * 4);
            #pragma unroll
            for (int ws = 0; ws < 3; ws++) {
                const float* Wp = (ws == 0) ? Wq : ((ws == 1) ? Wk : Wv);
                #pragma unroll
                for (int i = 0; i < 4; i++)
                    wr[ws][i] = *(const float4*)(Wp + (size_t)(k1 + xrow + i * 16) * HS + xq4 * 4);
            }
        }

        const uint32_t xhi_u = base_u, xlo_u = base_u + 16384;
        const uint32_t whi_u = base_u + 32768, wlo_u = base_u + 57344;
        #pragma unroll
        for (int kc = 0; kc < 4; kc++) {
            uint32_t ah[4], al4[4];
            ldsm4(ah,  a_addr(xhi_u, lane, wm, kc * 2));
            ldsm4(al4, a_addr(xlo_u, lane, wm, kc * 2));
            #pragma unroll
            for (int p = 0; p < 12; p++) {
                int gnt  = 2 * p;
                int wsel = gnt >> 3;
                int lnt  = gnt & 7;
                uint32_t bh[4], bl[4];
                ldsm4t(bh, bw_addr(whi_u + wsel * 8192, lane, kc * 16, lnt));
                ldsm4t(bl, bw_addr(wlo_u + wsel * 8192, lane, kc * 16, lnt));
                #pragma unroll
                for (int i = 0; i < 2; i++) {
                    int ln = gnt + i;
                    mma16816(acc[ln], ah,  &bh[2 * i]);
                    mma16816(acc[ln], ah,  &bl[2 * i]);
                    mma16816(acc[ln], al4, &bh[2 * i]);
                }
            }
        }
        // no trailing sync: next iteration writes the OTHER stage, and its
        // sync proves every warp finished this stage's mma before reuse.
    }

    #pragma unroll
    for (int nt = 0; nt < 24; nt++) {
        int wsel = nt >> 3;
        int col  = (nt & 7) * 8 + 2 * tg;
        float* op = (wsel == 0) ? g_q : ((wsel == 1) ? g_k : g_v);
        float b0 = bias_s[wsel * 64 + col];
        float b1 = bias_s[wsel * 64 + col + 1];
        float2 o0 = make_float2(acc[nt][0] + b0, acc[nt][1] + b1);
        float2 o1 = make_float2(acc[nt][2] + b0, acc[nt][3] + b1);
        *(float2*)(op + (size_t)(m0 + wm + g)     * HS + col) = o0;
        *(float2*)(op + (size_t)(m0 + wm + g + 8) * HS + col) = o1;
    }
}

// ===========================================================================
// Softmax + PV for one key tile (consumer warp, fragment-resident).
// sa holds scaled/masked S for that tile; o accumulated output.
// ===========================================================================
__device__ __forceinline__ void softmax_pv(
    float sa[8][4], float o[8][4],
    float& mr0, float& mr1, float& lr0, float& lr1,
    uint32_t Vhi_u, uint32_t Vlo_u, int lane)
{
    float tm0 = -1e30f, tm1 = -1e30f;
    #pragma unroll
    for (int nt = 0; nt < 8; nt++) {
        tm0 = fmaxf(tm0, fmaxf(sa[nt][0], sa[nt][1]));
        tm1 = fmaxf(tm1, fmaxf(sa[nt][2], sa[nt][3]));
    }
    tm0 = fmaxf(tm0, __shfl_xor_sync(0xffffffffu, tm0, 1));
    tm0 = fmaxf(tm0, __shfl_xor_sync(0xffffffffu, tm0, 2));
    tm1 = fmaxf(tm1, __shfl_xor_sync(0xffffffffu, tm1, 1));
    tm1 = fmaxf(tm1, __shfl_xor_sync(0xffffffffu, tm1, 2));
    float mn0 = fmaxf(mr0, tm0), mn1 = fmaxf(mr1, tm1);
    float al0 = __expf(mr0 - mn0), al1 = __expf(mr1 - mn1);
    mr0 = mn0; mr1 = mn1;
    float rs0 = 0.f, rs1 = 0.f;
    #pragma unroll
    for (int nt = 0; nt < 8; nt++) {
        sa[nt][0] = __expf(sa[nt][0] - mn0);
        sa[nt][1] = __expf(sa[nt][1] - mn0);
        sa[nt][2] = __expf(sa[nt][2] - mn1);
        sa[nt][3] = __expf(sa[nt][3] - mn1);
        rs0 += sa[nt][0] + sa[nt][1];
        rs1 += sa[nt][2] + sa[nt][3];
    }
    rs0 += __shfl_xor_sync(0xffffffffu, rs0, 1);
    rs0 += __shfl_xor_sync(0xffffffffu, rs0, 2);
    rs1 += __shfl_xor_sync(0xffffffffu, rs1, 1);
    rs1 += __shfl_xor_sync(0xffffffffu, rs1, 2);
    lr0 = lr0 * al0 + rs0;
    lr1 = lr1 * al1 + rs1;
    #pragma unroll
    for (int ct = 0; ct < 8; ct++) {
        o[ct][0] *= al0; o[ct][1] *= al0;
        o[ct][2] *= al1; o[ct][3] *= al1;
    }

    // O += P V ; P repacked accum->A-frags in registers
    #pragma unroll
    for (int kp = 0; kp < 2; kp++) {
        uint32_t ph[2][4], pl[2][4];
        #pragma unroll
        for (int i = 0; i < 2; i++) {
            int t0 = 4 * kp + 2 * i;
            ph[i][0] = pk2(sa[t0][0], sa[t0][1]);
            ph[i][1] = pk2(sa[t0][2], sa[t0][3]);
            ph[i][2] = pk2(sa[t0 + 1][0], sa[t0 + 1][1]);
            ph[i][3] = pk2(sa[t0 + 1][2], sa[t0 + 1][3]);
            pl[i][0] = pk2(sa[t0][0] - bhi(sa[t0][0]), sa[t0][1] - bhi(sa[t0][1]));
            pl[i][1] = pk2(sa[t0][2] - bhi(sa[t0][2]), sa[t0][3] - bhi(sa[t0][3]));
            pl[i][2] = pk2(sa[t0 + 1][0] - bhi(sa[t0 + 1][0]), sa[t0 + 1][1] - bhi(sa[t0 + 1][1]));
            pl[i][3] = pk2(sa[t0 + 1][2] - bhi(sa[t0 + 1][2]), sa[t0 + 1][3] - bhi(sa[t0 + 1][3]));
        }
        #pragma unroll
        for (int ct = 0; ct < 8; ct++) {
            uint32_t vh[4], vl[4];
            ldsm4t(vh, bv_addr(Vhi_u, lane, kp * 32, ct));
            ldsm4t(vl, bv_addr(Vlo_u, lane, kp * 32, ct));
            #pragma unroll
            for (int i = 0; i < 2; i++) {
                mma16816(o[ct], ph[i], &vh[2 * i]);
                mma16816(o[ct], ph[i], &vl[2 * i]);
                mma16816(o[ct], pl[i], &vh[2 * i]);
            }
        }
    }
}

// ===========================================================================
// Kernel 2: flash attention, warp-specialized, software-pipelined.
// Warps 0-3: compute. Per iteration: issue S_j mma (tensor pipe busy), run
//   softmax_{j-1} (ALU/MUFU overlapped), then PV_{j-1}. Persistent Q frags.
// Warps 4-7: producers, TRIPLE-buffered K/V (consumer reads K_j and V_{j-1}
//   while producer writes buf j+1 -- 3 live buffers).
// 1 CTA/SM, ~200 regs.
// ===========================================================================
// smem: Qhi 0, Qlo 8192; buf t at 16384+t*32768: Khi+0 Klo+8192 Vhi+16384 Vlo+24576
#define ATTN_SMEM_BYTES (16384 + 3 * 32768)

__global__ __launch_bounds__(256) void attn_mma(float* __restrict__ out)
{
    extern __shared__ char sm[];
    const uint32_t sm_u = smem_u32(sm);

    const int tid  = threadIdx.x;
    const int wid  = tid >> 5;
    const int lane = tid & 31;
    const int g    = lane >> 2;
    const int tg   = lane & 3;
    const bool consumer = (wid < 4);
    const int wm   = 16 * wid;          // consumer row base (wid 0..3)
    const int ptid = tid & 127;         // producer-local tid

    const int b    = blockIdx.y;
    const int pair = blockIdx.x;        // 0..31

    const float* qb = g_q + (size_t)b * TT * HS;
    const float* kb = g_k + (size_t)b * TT * HS;
    const float* vb = g_v + (size_t)b * TT * HS;
    float*       ob = out + (size_t)b * TT * HS;

    for (int half = 0; half < 2; half++) {
        const int qtile = half ? (TT / 64 - 1 - pair) : pair;
        const int m0 = qtile * 64;

        __syncthreads();   // all reads of Q/K/V buffers from previous half done

        if (consumer) {
            // consumers load Q tile (128 threads, 8 float4 each)
            #pragma unroll
            for (int i = 0; i < 8; i++) {
                int f = ptid + i * 128;
                int row = f >> 4, q4 = f & 15;
                float4 v = *(const float4*)(qb + (size_t)(m0 + row) * HS + q4 * 4);
                split_store(sm, sm + 8192, row, q4, v);
            }
        } else {
            // producers prefill buf 0 with K/V tile j=0
            char* kbase = sm + 16384;
            #pragma unroll
            for (int i = 0; i < 8; i++) {
                int f = ptid + i * 128;
                int row = f >> 4, q4 = f & 15;
                float4 kv4 = *(const float4*)(kb + (size_t)row * HS + q4 * 4);
                float4 vv4 = *(const float4*)(vb + (size_t)row * HS + q4 * 4);
                split_store(kbase,         kbase + 8192,  row, q4, kv4);
                split_store(kbase + 16384, kbase + 24576, row, q4, vv4);
            }
        }
        __syncthreads();

        // consumer persistent state
        uint32_t qh[4][4], ql[4][4];
        float sa[8][4], o[8][4];
        float mr0 = -1e30f, mr1 = -1e30f, lr0 = 0.f, lr1 = 0.f;
        if (consumer) {
            #pragma unroll
            for (int kc = 0; kc < 4; kc++) {
                ldsm4(qh[kc], a_addr(sm_u,        lane, wm, kc * 2));
                ldsm4(ql[kc], a_addr(sm_u + 8192, lane, wm, kc * 2));
            }
            #pragma unroll
            for (int ct = 0; ct < 8; ct++)
                #pragma unroll
                for (int c = 0; c < 4; c++) o[ct][c] = 0.f;
        }

        int bK = 0;        // buffer holding K_j (consumer view)
        int bP = 1;        // buffer producer fills (tile j+1)

        for (int j = 0; j <= qtile; j++) {
            if (!consumer) {
                if (j < qtile) {
                    const int n0n = (j + 1) * 64;
                    char* kbase = sm + 16384 + bP * 32768;
                    #pragma unroll
                    for (int i = 0; i < 8; i++) {
                        int f = ptid + i * 128;
                        int row = f >> 4, q4 = f & 15;
                        float4 kv4 = *(const float4*)(kb + (size_t)(n0n + row) * HS + q4 * 4);
                        float4 vv4 = *(const float4*)(vb + (size_t)(n0n + row) * HS + q4 * 4);
                        split_store(kbase,         kbase + 8192,  row, q4, kv4);
                        split_store(kbase + 16384, kbase + 24576, row, q4, vv4);
                    }
                }
            } else {
                const uint32_t kbu = sm_u + 16384 + bK * 32768;
                const uint32_t Khi_u = kbu, Klo_u = kbu + 8192;

                // ---- S_j = Q K_j^T into sb (tensor pipe loaded first) ----
                float sb[8][4];
                #pragma unroll
                for (int nt = 0; nt < 8; nt++)
                    #pragma unroll
                    for (int c = 0; c < 4; c++) sb[nt][c] = 0.f;

                #pragma unroll
                for (int kc = 0; kc < 4; kc++) {
                    #pragma unroll
                    for (int ntp = 0; ntp < 4; ntp++) {
                        uint32_t kh[4], kl4[4];
                        ldsm4(kh,  bk_addr(Khi_u, lane, 16 * ntp, kc * 2));
                        ldsm4(kl4, bk_addr(Klo_u, lane, 16 * ntp, kc * 2));
                        #pragma unroll
                        for (int i = 0; i < 2; i++) {
                            int nt = 2 * ntp + i;
                            mma16816(sb[nt], qh[kc], &kh[2 * i]);
                            mma16816(sb[nt], qh[kc], &kl4[2 * i]);
                            mma16816(sb[nt], ql[kc], &kh[2 * i]);
                        }
                    }
                }

                // ---- scale + causal mask for tile j ----
                if (j == qtile) {
                    #pragma unroll
                    for (int nt = 0; nt < 8; nt++) {
                        int c0 = nt * 8 + 2 * tg;
                        sb[nt][0] = (c0     <= wm + g)     ? sb[nt][0] * SCALE : -1e30f;
                        sb[nt][1] = (c0 + 1 <= wm + g)     ? sb[nt][1] * SCALE : -1e30f;
                        sb[nt][2] = (c0     <= wm + g + 8) ? sb[nt][2] * SCALE : -1e30f;
                        sb[nt][3] = (c0 + 1 <= wm + g + 8) ? sb[nt][3] * SCALE : -1e30f;
                    }
                } else {
                    #pragma unroll
                    for (int nt = 0; nt < 8; nt++)
                        #pragma unroll
                        for (int c = 0; c < 4; c++) sb[nt][c] *= SCALE;
                }

                // ---- softmax + PV for tile j-1 (overlaps S_j tensor exec) ----
                if (j > 0) {
                    int bV = bK == 0 ? 2 : bK - 1;   // buffer of tile j-1
                    const uint32_t vbu = sm_u + 16384 + bV * 32768;
                    softmax_pv(sa, o, mr0, mr1, lr0, lr1,
                               vbu + 16384, vbu + 24576, lane);
                }

                // carry S_j into sa
                #pragma unroll
                for (int nt = 0; nt < 8; nt++)
                    #pragma unroll
                    for (int c = 0; c < 4; c++) sa[nt][c] = sb[nt][c];
            }
            __syncthreads();
            bK = (bK == 2) ? 0 : bK + 1;
            bP = (bP == 2) ? 0 : bP + 1;
        }

        // ---- tail: softmax + PV for tile qtile (its V buffer is untouched
        //      until the next half's first barrier) ----
        if (consumer) {
            int bV = (bK == 0) ? 2 : bK - 1;   // buffer of tile qtile
            const uint32_t vbu = sm_u + 16384 + bV * 32768;
            softmax_pv(sa, o, mr0, mr1, lr0, lr1,
                       vbu + 16384, vbu + 24576, lane);

            float inv0 = 1.0f / lr0, inv1 = 1.0f / lr1;
            #pragma unroll
            for (int ct = 0; ct < 8; ct++) {
                int col = ct * 8 + 2 * tg;
                float2 o0 = make_float2(o[ct][0] * inv0, o[ct][1] * inv0);
                float2 o1 = make_float2(o[ct][2] * inv1, o[ct][3] * inv1);
                *(float2*)(ob + (size_t)(m0 + wm + g)     * HS + col) = o0;
                *(float2*)(ob + (size_t)(m0 + wm + g + 8) * HS + col) = o1;
            }
        }
    }
}

// ---------------------------------------------------------------------------
extern "C" void kernel_launch(void* const* d_in, const int* in_sizes, int n_in,
                              void* d_out, int out_size)
{
    const float* x  = (const float*)d_in[0];
    const float* Wq = (const float*)d_in[1];
    const float* bq = (const float*)d_in[2];
    const float* Wk = (const float*)d_in[3];
    const float* bk = (const float*)d_in[4];
    const float* Wv = (const float*)d_in[5];
    const float* bv = (const float*)d_in[6];
    float* out = (float*)d_out;

    (void)cudaFuncSetAttribute(qkv_mma,
                               cudaFuncAttributeMaxDynamicSharedMemorySize,
                               QKV_SMEM_BYTES);
    (void)cudaFuncSetAttribute(attn_mma,
                               cudaFuncAttributeMaxDynamicSharedMemorySize,
                               ATTN_SMEM_BYTES);

    qkv_mma<<<(BB * TT) / 128, 256, QKV_SMEM_BYTES>>>(x, Wq, bq, Wk, bk, Wv, bv);
    attn_mma<<<dim3(TT / 64 / 2, BB), 256, ATTN_SMEM_BYTES>>>(out);
}

// round 13
// speedup vs baseline: 1.0991x; 1.0391x over previous
#include <cuda_runtime.h>
#include <cuda_bf16.h>
#include <cstdint>

#define BB 4
#define TT 4096
#define CC 1024
#define HS 64
#define SCALE 0.03125f   // CC^-0.5 = 1/32 (reference scales by n_embd, not head_size)

// Scratch for q,k,v projections: [B,T,HS] fp32 each
__device__ float g_q[BB * TT * HS];
__device__ float g_k[BB * TT * HS];
__device__ float g_v[BB * TT * HS];

// ===========================================================================
// mma.sync / ldmatrix helpers (base PTX, legal on plain sm_100)
// ===========================================================================
__device__ __forceinline__ uint32_t smem_u32(const void* p) {
    uint32_t a;
    asm("{ .reg .u64 t; cvta.to.shared.u64 t, %1; cvt.u32.u64 %0, t; }"
        : "=r"(a) : "l"(p));
    return a;
}

__device__ __forceinline__ void ldsm4(uint32_t* r, uint32_t a) {
    asm volatile("ldmatrix.sync.aligned.m8n8.x4.shared.b16 {%0,%1,%2,%3}, [%4];"
        : "=r"(r[0]), "=r"(r[1]), "=r"(r[2]), "=r"(r[3]) : "r"(a));
}
__device__ __forceinline__ void ldsm4t(uint32_t* r, uint32_t a) {
    asm volatile("ldmatrix.sync.aligned.m8n8.x4.trans.shared.b16 {%0,%1,%2,%3}, [%4];"
        : "=r"(r[0]), "=r"(r[1]), "=r"(r[2]), "=r"(r[3]) : "r"(a));
}
// D += A*B, m16n8k16 bf16, fp32 accum (in-place)
__device__ __forceinline__ void mma16816(float* d, const uint32_t* a, const uint32_t* b) {
    asm volatile(
        "mma.sync.aligned.m16n8k16.row.col.f32.bf16.bf16.f32 "
        "{%0,%1,%2,%3}, {%4,%5,%6,%7}, {%8,%9}, {%0,%1,%2,%3};"
        : "+f"(d[0]), "+f"(d[1]), "+f"(d[2]), "+f"(d[3])
        : "r"(a[0]), "r"(a[1]), "r"(a[2]), "r"(a[3]), "r"(b[0]), "r"(b[1]));
}

__device__ __forceinline__ uint32_t pk2(float x, float y) {
    __nv_bfloat162 t = __floats2bfloat162_rn(x, y);
    return *reinterpret_cast<uint32_t*>(&t);
}
__device__ __forceinline__ float bhi(float x) {
    return __bfloat162float(__float2bfloat16_rn(x));
}

// All bf16 tiles: row-major, 64 cols = 128B rows, 16B chunks swizzled chunk^=(row&7)
// A-operand x4 (non-trans)
__device__ __forceinline__ uint32_t a_addr(uint32_t base, int lane, int mbase, int cbase) {
    int t = lane >> 3, r = lane & 7;
    int row = mbase + ((t & 1) << 3) + r;
    int chunk = cbase + (t >> 1);
    return base + row * 128 + (((chunk ^ (row & 7))) << 4);
}
// B from K-style storage [n][k] (non-trans): 2 n-tiles x k16
__device__ __forceinline__ uint32_t bk_addr(uint32_t base, int lane, int nbase, int cbase) {
    int t = lane >> 3, r = lane & 7;
    int row = nbase + ((t >> 1) << 3) + r;
    int chunk = cbase + (t & 1);
    return base + row * 128 + (((chunk ^ (row & 7))) << 4);
}
// B from V-style storage [k][n] (.trans): k32 x one 8-col chunk
__device__ __forceinline__ uint32_t bv_addr(uint32_t base, int lane, int krow0, int chunk) {
    int t = lane >> 3, r = lane & 7;
    int row = krow0 + ((t >> 1) << 4) + ((t & 1) << 3) + r;
    return base + row * 128 + (((chunk ^ (row & 7))) << 4);
}
// B from W-style storage [k][n] (.trans): fixed k16, 2 n-tiles
__device__ __forceinline__ uint32_t bw_addr(uint32_t base, int lane, int krow0, int ntchunk0) {
    int t = lane >> 3, r = lane & 7;
    int row = krow0 + ((t & 1) << 3) + r;
    int chunk = ntchunk0 + (t >> 1);
    return base + row * 128 + (((chunk ^ (row & 7))) << 4);
}

// split fp32 float4 -> hi/lo bf16x4 (8B each) and store at swizzled offset
__device__ __forceinline__ void split_store(char* hi_b, char* lo_b, int row, int q4, float4 v) {
    uint32_t off = (uint32_t)(row * 128 + ((((q4 >> 1) ^ (row & 7))) << 4) + ((q4 & 1) << 3));
    uint2 h, l;
    h.x = pk2(v.x, v.y); h.y = pk2(v.z, v.w);
    l.x = pk2(v.x - bhi(v.x), v.y - bhi(v.y));
    l.y = pk2(v.z - bhi(v.z), v.w - bhi(v.w));
    *(uint2*)(hi_b + off) = h;
    *(uint2*)(lo_b + off) = l;
}

// ===========================================================================
// Kernel 1: QKV projection, mma.sync bf16 3-product.  (unchanged from R10 PASS)
// CTA: M=128 rows, N=192, K=1024 in 16 stages of 64 -> 128 CTAs = 1 wave.
// BOTH x and W prefetched into registers each stage.
// ===========================================================================
// per-stage: XHI 0 (16K), XLO 16384 (16K), WHI 32768 (3x8K), WLO 57344 (3x8K)
#define QKV_STAGE 81920
#define QKV_SMEM_BYTES (2 * QKV_STAGE + 768)

__global__ __launch_bounds__(256) void qkv_mma(
    const float* __restrict__ x,
    const float* __restrict__ Wq, const float* __restrict__ bq,
    const float* __restrict__ Wk, const float* __restrict__ bk,
    const float* __restrict__ Wv, const float* __restrict__ bv)
{
    extern __shared__ char sm[];
    float* bias_s = (float*)(sm + 2 * QKV_STAGE);

    const uint32_t sm_u = smem_u32(sm);
    const int tid  = threadIdx.x;
    const int wid  = tid >> 5;
    const int lane = tid & 31;
    const int tg   = lane & 3;
    const int g    = lane >> 2;
    const int m0   = blockIdx.x * 128;
    const int wm   = 16 * wid;
    const int xrow = tid >> 4, xq4 = tid & 15;

    if (tid < 192) {
        const float* bp = (tid < 64) ? bq : ((tid < 128) ? bk : bv);
        bias_s[tid] = bp[tid & 63];
    }

    float4 xr[8];
    float4 wr[3][4];
    #pragma unroll
    for (int i = 0; i < 8; i++)
        xr[i] = *(const float4*)(x + (size_t)(m0 + xrow + i * 16) * CC + xq4 * 4);
    #pragma unroll
    for (int ws = 0; ws < 3; ws++) {
        const float* Wp = (ws == 0) ? Wq : ((ws == 1) ? Wk : Wv);
        #pragma unroll
        for (int i = 0; i < 4; i++)
            wr[ws][i] = *(const float4*)(Wp + (size_t)(xrow + i * 16) * HS + xq4 * 4);
    }

    float acc[24][4];
    #pragma unroll
    for (int i = 0; i < 24; i++)
        #pragma unroll
        for (int c = 0; c < 4; c++) acc[i][c] = 0.f;

    for (int kb = 0; kb < 16; kb++) {
        const int st = kb & 1;
        char* base = sm + st * QKV_STAGE;
        const uint32_t base_u = sm_u + st * QKV_STAGE;

        #pragma unroll
        for (int i = 0; i < 8; i++)
            split_store(base, base + 16384, xrow + i * 16, xq4, xr[i]);
        #pragma unroll
        for (int ws = 0; ws < 3; ws++)
            #pragma unroll
            for (int i = 0; i < 4; i++)
                split_store(base + 32768 + ws * 8192, base + 57344 + ws * 8192,
                            xrow + i * 16, xq4, wr[ws][i]);
        __syncthreads();

        if (kb < 15) {
            const int k1 = (kb + 1) * 64;
            #pragma unroll
            for (int i = 0; i < 8; i++)
                xr[i] = *(const float4*)(x + (size_t)(m0 + xrow + i * 16) * CC + k1 + xq4 * 4);
            #pragma unroll
            for (int ws = 0; ws < 3; ws++) {
                const float* Wp = (ws == 0) ? Wq : ((ws == 1) ? Wk : Wv);
                #pragma unroll
                for (int i = 0; i < 4; i++)
                    wr[ws][i] = *(const float4*)(Wp + (size_t)(k1 + xrow + i * 16) * HS + xq4 * 4);
            }
        }

        const uint32_t xhi_u = base_u, xlo_u = base_u + 16384;
        const uint32_t whi_u = base_u + 32768, wlo_u = base_u + 57344;
        #pragma unroll
        for (int kc = 0; kc < 4; kc++) {
            uint32_t ah[4], al4[4];
            ldsm4(ah,  a_addr(xhi_u, lane, wm, kc * 2));
            ldsm4(al4, a_addr(xlo_u, lane, wm, kc * 2));
            #pragma unroll
            for (int p = 0; p < 12; p++) {
                int gnt  = 2 * p;
                int wsel = gnt >> 3;
                int lnt  = gnt & 7;
                uint32_t bh[4], bl[4];
                ldsm4t(bh, bw_addr(whi_u + wsel * 8192, lane, kc * 16, lnt));
                ldsm4t(bl, bw_addr(wlo_u + wsel * 8192, lane, kc * 16, lnt));
                #pragma unroll
                for (int i = 0; i < 2; i++) {
                    int ln = gnt + i;
                    mma16816(acc[ln], ah,  &bh[2 * i]);
                    mma16816(acc[ln], ah,  &bl[2 * i]);
                    mma16816(acc[ln], al4, &bh[2 * i]);
                }
            }
        }
    }

    #pragma unroll
    for (int nt = 0; nt < 24; nt++) {
        int wsel = nt >> 3;
        int col  = (nt & 7) * 8 + 2 * tg;
        float* op = (wsel == 0) ? g_q : ((wsel == 1) ? g_k : g_v);
        float b0 = bias_s[wsel * 64 + col];
        float b1 = bias_s[wsel * 64 + col + 1];
        float2 o0 = make_float2(acc[nt][0] + b0, acc[nt][1] + b1);
        float2 o1 = make_float2(acc[nt][2] + b0, acc[nt][3] + b1);
        *(float2*)(op + (size_t)(m0 + wm + g)     * HS + col) = o0;
        *(float2*)(op + (size_t)(m0 + wm + g + 8) * HS + col) = o1;
    }
}

// ===========================================================================
// Softmax + PV for one key tile (consumer warp, fragment-resident).
// ===========================================================================
__device__ __forceinline__ void softmax_pv(
    float (&sa)[8][4], float (&o)[8][4],
    float& mr0, float& mr1, float& lr0, float& lr1,
    uint32_t Vhi_u, uint32_t Vlo_u, int lane)
{
    float tm0 = -1e30f, tm1 = -1e30f;
    #pragma unroll
    for (int nt = 0; nt < 8; nt++) {
        tm0 = fmaxf(tm0, fmaxf(sa[nt][0], sa[nt][1]));
        tm1 = fmaxf(tm1, fmaxf(sa[nt][2], sa[nt][3]));
    }
    tm0 = fmaxf(tm0, __shfl_xor_sync(0xffffffffu, tm0, 1));
    tm0 = fmaxf(tm0, __shfl_xor_sync(0xffffffffu, tm0, 2));
    tm1 = fmaxf(tm1, __shfl_xor_sync(0xffffffffu, tm1, 1));
    tm1 = fmaxf(tm1, __shfl_xor_sync(0xffffffffu, tm1, 2));
    float mn0 = fmaxf(mr0, tm0), mn1 = fmaxf(mr1, tm1);
    float al0 = __expf(mr0 - mn0), al1 = __expf(mr1 - mn1);
    mr0 = mn0; mr1 = mn1;
    float rs0 = 0.f, rs1 = 0.f;
    #pragma unroll
    for (int nt = 0; nt < 8; nt++) {
        sa[nt][0] = __expf(sa[nt][0] - mn0);
        sa[nt][1] = __expf(sa[nt][1] - mn0);
        sa[nt][2] = __expf(sa[nt][2] - mn1);
        sa[nt][3] = __expf(sa[nt][3] - mn1);
        rs0 += sa[nt][0] + sa[nt][1];
        rs1 += sa[nt][2] + sa[nt][3];
    }
    rs0 += __shfl_xor_sync(0xffffffffu, rs0, 1);
    rs0 += __shfl_xor_sync(0xffffffffu, rs0, 2);
    rs1 += __shfl_xor_sync(0xffffffffu, rs1, 1);
    rs1 += __shfl_xor_sync(0xffffffffu, rs1, 2);
    lr0 = lr0 * al0 + rs0;
    lr1 = lr1 * al1 + rs1;
    #pragma unroll
    for (int ct = 0; ct < 8; ct++) {
        o[ct][0] *= al0; o[ct][1] *= al0;
        o[ct][2] *= al1; o[ct][3] *= al1;
    }

    // O += P V ; P repacked accum->A-frags in registers
    #pragma unroll
    for (int kp = 0; kp < 2; kp++) {
        uint32_t ph[2][4], pl[2][4];
        #pragma unroll
        for (int i = 0; i < 2; i++) {
            int t0 = 4 * kp + 2 * i;
            ph[i][0] = pk2(sa[t0][0], sa[t0][1]);
            ph[i][1] = pk2(sa[t0][2], sa[t0][3]);
            ph[i][2] = pk2(sa[t0 + 1][0], sa[t0 + 1][1]);
            ph[i][3] = pk2(sa[t0 + 1][2], sa[t0 + 1][3]);
            pl[i][0] = pk2(sa[t0][0] - bhi(sa[t0][0]), sa[t0][1] - bhi(sa[t0][1]));
            pl[i][1] = pk2(sa[t0][2] - bhi(sa[t0][2]), sa[t0][3] - bhi(sa[t0][3]));
            pl[i][2] = pk2(sa[t0 + 1][0] - bhi(sa[t0 + 1][0]), sa[t0 + 1][1] - bhi(sa[t0 + 1][1]));
            pl[i][3] = pk2(sa[t0 + 1][2] - bhi(sa[t0 + 1][2]), sa[t0 + 1][3] - bhi(sa[t0 + 1][3]));
        }
        #pragma unroll
        for (int ct = 0; ct < 8; ct++) {
            uint32_t vh[4], vl[4];
            ldsm4t(vh, bv_addr(Vhi_u, lane, kp * 32, ct));
            ldsm4t(vl, bv_addr(Vlo_u, lane, kp * 32, ct));
            #pragma unroll
            for (int i = 0; i < 2; i++) {
                mma16816(o[ct], ph[i], &vh[2 * i]);
                mma16816(o[ct], ph[i], &vl[2 * i]);
                mma16816(o[ct], pl[i], &vh[2 * i]);
            }
        }
    }
}

// ===========================================================================
// Consumer pipeline step for key tile j:
//   1. issue S_j mma into cur (tensor pipe loaded)
//   2. softmax+PV of tile j-1 from prev (ALU/MUFU overlaps S_j execution)
//   3. scale/mask cur (S_j results ready by now)
// ===========================================================================
__device__ __forceinline__ void consumer_step(
    float (&cur)[8][4], float (&prev)[8][4],
    int j, int qtile, uint32_t sm_u, int bK,
    const uint32_t (&qh)[4][4], const uint32_t (&ql)[4][4],
    float (&o)[8][4], float& mr0, float& mr1, float& lr0, float& lr1,
    int lane, int wm, int g, int tg)
{
    const uint32_t kbu = sm_u + 16384 + bK * 32768;
    const uint32_t Khi_u = kbu, Klo_u = kbu + 8192;

    // ---- 1. S_j = Q K_j^T into cur ----
    #pragma unroll
    for (int nt = 0; nt < 8; nt++)
        #pragma unroll
        for (int c = 0; c < 4; c++) cur[nt][c] = 0.f;

    #pragma unroll
    for (int kc = 0; kc < 4; kc++) {
        #pragma unroll
        for (int ntp = 0; ntp < 4; ntp++) {
            uint32_t kh[4], kl4[4];
            ldsm4(kh,  bk_addr(Khi_u, lane, 16 * ntp, kc * 2));
            ldsm4(kl4, bk_addr(Klo_u, lane, 16 * ntp, kc * 2));
            #pragma unroll
            for (int i = 0; i < 2; i++) {
                int nt = 2 * ntp + i;
                mma16816(cur[nt], qh[kc], &kh[2 * i]);
                mma16816(cur[nt], qh[kc], &kl4[2 * i]);
                mma16816(cur[nt], ql[kc], &kh[2 * i]);
            }
        }
    }

    // ---- 2. softmax + PV for tile j-1 (independent of cur) ----
    if (j > 0) {
        int bV = (bK == 0) ? 2 : bK - 1;
        const uint32_t vbu = sm_u + 16384 + bV * 32768;
        softmax_pv(prev, o, mr0, mr1, lr0, lr1, vbu + 16384, vbu + 24576, lane);
    }

    // ---- 3. scale + causal mask for cur ----
    if (j == qtile) {
        #pragma unroll
        for (int nt = 0; nt < 8; nt++) {
            int c0 = nt * 8 + 2 * tg;
            cur[nt][0] = (c0     <= wm + g)     ? cur[nt][0] * SCALE : -1e30f;
            cur[nt][1] = (c0 + 1 <= wm + g)     ? cur[nt][1] * SCALE : -1e30f;
            cur[nt][2] = (c0     <= wm + g + 8) ? cur[nt][2] * SCALE : -1e30f;
            cur[nt][3] = (c0 + 1 <= wm + g + 8) ? cur[nt][3] * SCALE : -1e30f;
        }
    } else {
        #pragma unroll
        for (int nt = 0; nt < 8; nt++)
            #pragma unroll
            for (int c = 0; c < 4; c++) cur[nt][c] *= SCALE;
    }
}

// ===========================================================================
// Kernel 2: flash attention, warp-specialized, software-pipelined (fixed order).
// Warps 0-3: compute (persistent Q frags; S register banks sA/sB alternate by
//   j parity so softmax_{j-1} overlaps S_j tensor execution; no copy).
// Warps 4-7: producers, TRIPLE-buffered K/V.
// 1 CTA/SM.
// ===========================================================================
// smem: Qhi 0, Qlo 8192; buf t at 16384+t*32768: Khi+0 Klo+8192 Vhi+16384 Vlo+24576
#define ATTN_SMEM_BYTES (16384 + 3 * 32768)

__global__ __launch_bounds__(256) void attn_mma(float* __restrict__ out)
{
    extern __shared__ char sm[];
    const uint32_t sm_u = smem_u32(sm);

    const int tid  = threadIdx.x;
    const int wid  = tid >> 5;
    const int lane = tid & 31;
    const int g    = lane >> 2;
    const int tg   = lane & 3;
    const bool consumer = (wid < 4);
    const int wm   = 16 * wid;          // consumer row base (wid 0..3)
    const int ptid = tid & 127;         // producer-local tid

    const int b    = blockIdx.y;
    const int pair = blockIdx.x;        // 0..31

    const float* qb = g_q + (size_t)b * TT * HS;
    const float* kb = g_k + (size_t)b * TT * HS;
    const float* vb = g_v + (size_t)b * TT * HS;
    float*       ob = out + (size_t)b * TT * HS;

    for (int half = 0; half < 2; half++) {
        const int qtile = half ? (TT / 64 - 1 - pair) : pair;
        const int m0 = qtile * 64;

        __syncthreads();   // all reads of Q/K/V buffers from previous half done

        if (consumer) {
            #pragma unroll
            for (int i = 0; i < 8; i++) {
                int f = ptid + i * 128;
                int row = f >> 4, q4 = f & 15;
                float4 v = *(const float4*)(qb + (size_t)(m0 + row) * HS + q4 * 4);
                split_store(sm, sm + 8192, row, q4, v);
            }
        } else {
            char* kbase = sm + 16384;
            #pragma unroll
            for (int i = 0; i < 8; i++) {
                int f = ptid + i * 128;
                int row = f >> 4, q4 = f & 15;
                float4 kv4 = *(const float4*)(kb + (size_t)row * HS + q4 * 4);
                float4 vv4 = *(const float4*)(vb + (size_t)row * HS + q4 * 4);
                split_store(kbase,         kbase + 8192,  row, q4, kv4);
                split_store(kbase + 16384, kbase + 24576, row, q4, vv4);
            }
        }
        __syncthreads();

        // consumer persistent state
        uint32_t qh[4][4], ql[4][4];
        float sA[8][4], sB[8][4], o[8][4];
        float mr0 = -1e30f, mr1 = -1e30f, lr0 = 0.f, lr1 = 0.f;
        if (consumer) {
            #pragma unroll
            for (int kc = 0; kc < 4; kc++) {
                ldsm4(qh[kc], a_addr(sm_u,        lane, wm, kc * 2));
                ldsm4(ql[kc], a_addr(sm_u + 8192, lane, wm, kc * 2));
            }
            #pragma unroll
            for (int ct = 0; ct < 8; ct++)
                #pragma unroll
                for (int c = 0; c < 4; c++) o[ct][c] = 0.f;
        }

        int bK = 0;        // buffer holding K_j (consumer view)
        int bP = 1;        // buffer producer fills (tile j+1)

        for (int j = 0; j <= qtile; j++) {
            if (!consumer) {
                if (j < qtile) {
                    const int n0n = (j + 1) * 64;
                    char* kbase = sm + 16384 + bP * 32768;
                    #pragma unroll
                    for (int i = 0; i < 8; i++) {
                        int f = ptid + i * 128;
                        int row = f >> 4, q4 = f & 15;
                        float4 kv4 = *(const float4*)(kb + (size_t)(n0n + row) * HS + q4 * 4);
                        float4 vv4 = *(const float4*)(vb + (size_t)(n0n + row) * HS + q4 * 4);
                        split_store(kbase,         kbase + 8192,  row, q4, kv4);
                        split_store(kbase + 16384, kbase + 24576, row, q4, vv4);
                    }
                }
            } else {
                if ((j & 1) == 0)
                    consumer_step(sA, sB, j, qtile, sm_u, bK, qh, ql,
                                  o, mr0, mr1, lr0, lr1, lane, wm, g, tg);
                else
                    consumer_step(sB, sA, j, qtile, sm_u, bK, qh, ql,
                                  o, mr0, mr1, lr0, lr1, lane, wm, g, tg);
            }
            __syncthreads();
            bK = (bK == 2) ? 0 : bK + 1;
            bP = (bP == 2) ? 0 : bP + 1;
        }

        // ---- tail: softmax + PV for tile qtile (V buffer untouched until
        //      the next half's first barrier) ----
        if (consumer) {
            const uint32_t vbu = sm_u + 16384 + (qtile % 3) * 32768;
            if ((qtile & 1) == 0)
                softmax_pv(sA, o, mr0, mr1, lr0, lr1, vbu + 16384, vbu + 24576, lane);
            else
                softmax_pv(sB, o, mr0, mr1, lr0, lr1, vbu + 16384, vbu + 24576, lane);

            float inv0 = 1.0f / lr0, inv1 = 1.0f / lr1;
            #pragma unroll
            for (int ct = 0; ct < 8; ct++) {
                int col = ct * 8 + 2 * tg;
                float2 o0 = make_float2(o[ct][0] * inv0, o[ct][1] * inv0);
                float2 o1 = make_float2(o[ct][2] * inv1, o[ct][3] * inv1);
                *(float2*)(ob + (size_t)(m0 + wm + g)     * HS + col) = o0;
                *(float2*)(ob + (size_t)(m0 + wm + g + 8) * HS + col) = o1;
            }
        }
    }
}

// ---------------------------------------------------------------------------
extern "C" void kernel_launch(void* const* d_in, const int* in_sizes, int n_in,
                              void* d_out, int out_size)
{
    const float* x  = (const float*)d_in[0];
    const float* Wq = (const float*)d_in[1];
    const float* bq = (const float*)d_in[2];
    const float* Wk = (const float*)d_in[3];
    const float* bk = (const float*)d_in[4];
    const float* Wv = (const float*)d_in[5];
    const float* bv = (const float*)d_in[6];
    float* out = (float*)d_out;

    (void)cudaFuncSetAttribute(qkv_mma,
                               cudaFuncAttributeMaxDynamicSharedMemorySize,
                               QKV_SMEM_BYTES);
    (void)cudaFuncSetAttribute(attn_mma,
                               cudaFuncAttributeMaxDynamicSharedMemorySize,
                               ATTN_SMEM_BYTES);

    qkv_mma<<<(BB * TT) / 128, 256, QKV_SMEM_BYTES>>>(x, Wq, bq, Wk, bk, Wv, bv);
    attn_mma<<<dim3(TT / 64 / 2, BB), 256, ATTN_SMEM_BYTES>>>(out);
}

// round 14
// speedup vs baseline: 1.2103x; 1.1012x over previous
#include <cuda_runtime.h>
#include <cuda_bf16.h>
#include <cstdint>

#define BB 4
#define TT 4096
#define CC 1024
#define HS 64
#define SCALE 0.03125f   // CC^-0.5 = 1/32 (reference scales by n_embd, not head_size)

// Scratch for q,k,v projections: [B,T,HS] fp32 each
__device__ float g_q[BB * TT * HS];
__device__ float g_k[BB * TT * HS];
__device__ float g_v[BB * TT * HS];

// ===========================================================================
// mma.sync / ldmatrix helpers (base PTX, legal on plain sm_100)
// ===========================================================================
__device__ __forceinline__ uint32_t smem_u32(const void* p) {
    uint32_t a;
    asm("{ .reg .u64 t; cvta.to.shared.u64 t, %1; cvt.u32.u64 %0, t; }"
        : "=r"(a) : "l"(p));
    return a;
}

__device__ __forceinline__ void ldsm4(uint32_t* r, uint32_t a) {
    asm volatile("ldmatrix.sync.aligned.m8n8.x4.shared.b16 {%0,%1,%2,%3}, [%4];"
        : "=r"(r[0]), "=r"(r[1]), "=r"(r[2]), "=r"(r[3]) : "r"(a));
}
__device__ __forceinline__ void ldsm4t(uint32_t* r, uint32_t a) {
    asm volatile("ldmatrix.sync.aligned.m8n8.x4.trans.shared.b16 {%0,%1,%2,%3}, [%4];"
        : "=r"(r[0]), "=r"(r[1]), "=r"(r[2]), "=r"(r[3]) : "r"(a));
}
// D += A*B, m16n8k16 bf16, fp32 accum (in-place)
__device__ __forceinline__ void mma16816(float* d, const uint32_t* a, const uint32_t* b) {
    asm volatile(
        "mma.sync.aligned.m16n8k16.row.col.f32.bf16.bf16.f32 "
        "{%0,%1,%2,%3}, {%4,%5,%6,%7}, {%8,%9}, {%0,%1,%2,%3};"
        : "+f"(d[0]), "+f"(d[1]), "+f"(d[2]), "+f"(d[3])
        : "r"(a[0]), "r"(a[1]), "r"(a[2]), "r"(a[3]), "r"(b[0]), "r"(b[1]));
}

__device__ __forceinline__ uint32_t pk2(float x, float y) {
    __nv_bfloat162 t = __floats2bfloat162_rn(x, y);
    return *reinterpret_cast<uint32_t*>(&t);
}
__device__ __forceinline__ float bhi(float x) {
    return __bfloat162float(__float2bfloat16_rn(x));
}

// All bf16 tiles: row-major, 64 cols = 128B rows, 16B chunks swizzled chunk^=(row&7)
// A-operand x4 (non-trans)
__device__ __forceinline__ uint32_t a_addr(uint32_t base, int lane, int mbase, int cbase) {
    int t = lane >> 3, r = lane & 7;
    int row = mbase + ((t & 1) << 3) + r;
    int chunk = cbase + (t >> 1);
    return base + row * 128 + (((chunk ^ (row & 7))) << 4);
}
// B from K-style storage [n][k] (non-trans): 2 n-tiles x k16
__device__ __forceinline__ uint32_t bk_addr(uint32_t base, int lane, int nbase, int cbase) {
    int t = lane >> 3, r = lane & 7;
    int row = nbase + ((t >> 1) << 3) + r;
    int chunk = cbase + (t & 1);
    return base + row * 128 + (((chunk ^ (row & 7))) << 4);
}
// B from V-style storage [k][n] (.trans): k32 x one 8-col chunk
__device__ __forceinline__ uint32_t bv_addr(uint32_t base, int lane, int krow0, int chunk) {
    int t = lane >> 3, r = lane & 7;
    int row = krow0 + ((t >> 1) << 4) + ((t & 1) << 3) + r;
    return base + row * 128 + (((chunk ^ (row & 7))) << 4);
}
// B from W-style storage [k][n] (.trans): fixed k16, 2 n-tiles
__device__ __forceinline__ uint32_t bw_addr(uint32_t base, int lane, int krow0, int ntchunk0) {
    int t = lane >> 3, r = lane & 7;
    int row = krow0 + ((t & 1) << 3) + r;
    int chunk = ntchunk0 + (t >> 1);
    return base + row * 128 + (((chunk ^ (row & 7))) << 4);
}

// split fp32 float4 -> hi/lo bf16x4 (8B each) and store at swizzled offset
__device__ __forceinline__ void split_store(char* hi_b, char* lo_b, int row, int q4, float4 v) {
    uint32_t off = (uint32_t)(row * 128 + ((((q4 >> 1) ^ (row & 7))) << 4) + ((q4 & 1) << 3));
    uint2 h, l;
    h.x = pk2(v.x, v.y); h.y = pk2(v.z, v.w);
    l.x = pk2(v.x - bhi(v.x), v.y - bhi(v.y));
    l.y = pk2(v.z - bhi(v.z), v.w - bhi(v.w));
    *(uint2*)(hi_b + off) = h;
    *(uint2*)(lo_b + off) = l;
}

// ===========================================================================
// Kernel 1: QKV projection, mma.sync bf16 3-product.  (byte-exact R13 PASS,
// measured ~57-63us)
// CTA: M=128 rows, N=192, K=1024 in 16 stages of 64 -> 128 CTAs = 1 wave.
// BOTH x and W prefetched into registers each stage.
// ===========================================================================
// per-stage: XHI 0 (16K), XLO 16384 (16K), WHI 32768 (3x8K), WLO 57344 (3x8K)
#define QKV_STAGE 81920
#define QKV_SMEM_BYTES (2 * QKV_STAGE + 768)

__global__ __launch_bounds__(256) void qkv_mma(
    const float* __restrict__ x,
    const float* __restrict__ Wq, const float* __restrict__ bq,
    const float* __restrict__ Wk, const float* __restrict__ bk,
    const float* __restrict__ Wv, const float* __restrict__ bv)
{
    extern __shared__ char sm[];
    float* bias_s = (float*)(sm + 2 * QKV_STAGE);

    const uint32_t sm_u = smem_u32(sm);
    const int tid  = threadIdx.x;
    const int wid  = tid >> 5;
    const int lane = tid & 31;
    const int tg   = lane & 3;
    const int g    = lane >> 2;
    const int m0   = blockIdx.x * 128;
    const int wm   = 16 * wid;
    const int xrow = tid >> 4, xq4 = tid & 15;

    if (tid < 192) {
        const float* bp = (tid < 64) ? bq : ((tid < 128) ? bk : bv);
        bias_s[tid] = bp[tid & 63];
    }

    float4 xr[8];
    float4 wr[3][4];
    #pragma unroll
    for (int i = 0; i < 8; i++)
        xr[i] = *(const float4*)(x + (size_t)(m0 + xrow + i * 16) * CC + xq4 * 4);
    #pragma unroll
    for (int ws = 0; ws < 3; ws++) {
        const float* Wp = (ws == 0) ? Wq : ((ws == 1) ? Wk : Wv);
        #pragma unroll
        for (int i = 0; i < 4; i++)
            wr[ws][i] = *(const float4*)(Wp + (size_t)(xrow + i * 16) * HS + xq4 * 4);
    }

    float acc[24][4];
    #pragma unroll
    for (int i = 0; i < 24; i++)
        #pragma unroll
        for (int c = 0; c < 4; c++) acc[i][c] = 0.f;

    for (int kb = 0; kb < 16; kb++) {
        const int st = kb & 1;
        char* base = sm + st * QKV_STAGE;
        const uint32_t base_u = sm_u + st * QKV_STAGE;

        #pragma unroll
        for (int i = 0; i < 8; i++)
            split_store(base, base + 16384, xrow + i * 16, xq4, xr[i]);
        #pragma unroll
        for (int ws = 0; ws < 3; ws++)
            #pragma unroll
            for (int i = 0; i < 4; i++)
                split_store(base + 32768 + ws * 8192, base + 57344 + ws * 8192,
                            xrow + i * 16, xq4, wr[ws][i]);
        __syncthreads();

        if (kb < 15) {
            const int k1 = (kb + 1) * 64;
            #pragma unroll
            for (int i = 0; i < 8; i++)
                xr[i] = *(const float4*)(x + (size_t)(m0 + xrow + i * 16) * CC + k1 + xq4 * 4);
            #pragma unroll
            for (int ws = 0; ws < 3; ws++) {
                const float* Wp = (ws == 0) ? Wq : ((ws == 1) ? Wk : Wv);
                #pragma unroll
                for (int i = 0; i < 4; i++)
                    wr[ws][i] = *(const float4*)(Wp + (size_t)(k1 + xrow + i * 16) * HS + xq4 * 4);
            }
        }

        const uint32_t xhi_u = base_u, xlo_u = base_u + 16384;
        const uint32_t whi_u = base_u + 32768, wlo_u = base_u + 57344;
        #pragma unroll
        for (int kc = 0; kc < 4; kc++) {
            uint32_t ah[4], al4[4];
            ldsm4(ah,  a_addr(xhi_u, lane, wm, kc * 2));
            ldsm4(al4, a_addr(xlo_u, lane, wm, kc * 2));
            #pragma unroll
            for (int p = 0; p < 12; p++) {
                int gnt  = 2 * p;
                int wsel = gnt >> 3;
                int lnt  = gnt & 7;
                uint32_t bh[4], bl[4];
                ldsm4t(bh, bw_addr(whi_u + wsel * 8192, lane, kc * 16, lnt));
                ldsm4t(bl, bw_addr(wlo_u + wsel * 8192, lane, kc * 16, lnt));
                #pragma unroll
                for (int i = 0; i < 2; i++) {
                    int ln = gnt + i;
                    mma16816(acc[ln], ah,  &bh[2 * i]);
                    mma16816(acc[ln], ah,  &bl[2 * i]);
                    mma16816(acc[ln], al4, &bh[2 * i]);
                }
            }
        }
    }

    #pragma unroll
    for (int nt = 0; nt < 24; nt++) {
        int wsel = nt >> 3;
        int col  = (nt & 7) * 8 + 2 * tg;
        float* op = (wsel == 0) ? g_q : ((wsel == 1) ? g_k : g_v);
        float b0 = bias_s[wsel * 64 + col];
        float b1 = bias_s[wsel * 64 + col + 1];
        float2 o0 = make_float2(acc[nt][0] + b0, acc[nt][1] + b1);
        float2 o1 = make_float2(acc[nt][2] + b0, acc[nt][3] + b1);
        *(float2*)(op + (size_t)(m0 + wm + g)     * HS + col) = o0;
        *(float2*)(op + (size_t)(m0 + wm + g + 8) * HS + col) = o1;
    }
}

// ===========================================================================
// Kernel 2: flash attention, warp-specialized.  (byte-exact R6 PASS, 123.1us)
// Warps 0-3: compute (16 rows x 64 cols each; fragment-resident softmax;
//            persistent Q frags; P repacked accum->A-frags in registers).
// Warps 4-7: producers (double-buffered K/V load+split).
// 1 __syncthreads per key tile.
// ===========================================================================
// smem: Qhi 0, Qlo 8192; buf s at 16384+s*32768: Khi+0 Klo+8192 Vhi+16384 Vlo+24576
#define ATTN_SMEM_BYTES (16384 + 2 * 32768)

__global__ __launch_bounds__(256) void attn_mma(float* __restrict__ out)
{
    extern __shared__ char sm[];
    const uint32_t sm_u = smem_u32(sm);

    const int tid  = threadIdx.x;
    const int wid  = tid >> 5;
    const int lane = tid & 31;
    const int g    = lane >> 2;
    const int tg   = lane & 3;
    const bool consumer = (wid < 4);
    const int wm   = 16 * wid;          // consumer row base (wid 0..3)
    const int ptid = tid & 127;         // producer-local tid

    const int b    = blockIdx.y;
    const int pair = blockIdx.x;        // 0..31

    const float* qb = g_q + (size_t)b * TT * HS;
    const float* kb = g_k + (size_t)b * TT * HS;
    const float* vb = g_v + (size_t)b * TT * HS;
    float*       ob = out + (size_t)b * TT * HS;

    for (int half = 0; half < 2; half++) {
        const int qtile = half ? (TT / 64 - 1 - pair) : pair;
        const int m0 = qtile * 64;

        __syncthreads();   // all reads of Q/K/V buffers from previous half done

        if (consumer) {
            // consumers load Q tile (128 threads, 8 float4 each)
            #pragma unroll
            for (int i = 0; i < 8; i++) {
                int f = ptid + i * 128;
                int row = f >> 4, q4 = f & 15;
                float4 v = *(const float4*)(qb + (size_t)(m0 + row) * HS + q4 * 4);
                split_store(sm, sm + 8192, row, q4, v);
            }
        } else {
            // producers prefill buf 0 with K/V tile j=0
            char* kbase = sm + 16384;
            #pragma unroll
            for (int i = 0; i < 8; i++) {
                int f = ptid + i * 128;
                int row = f >> 4, q4 = f & 15;
                float4 kv4 = *(const float4*)(kb + (size_t)row * HS + q4 * 4);
                float4 vv4 = *(const float4*)(vb + (size_t)row * HS + q4 * 4);
                split_store(kbase,         kbase + 8192,  row, q4, kv4);
                split_store(kbase + 16384, kbase + 24576, row, q4, vv4);
            }
        }
        __syncthreads();

        // consumer state
        uint32_t qh[4][4], ql[4][4];
        float o[8][4];
        float mr0 = -1e30f, mr1 = -1e30f, lr0 = 0.f, lr1 = 0.f;
        if (consumer) {
            #pragma unroll
            for (int kc = 0; kc < 4; kc++) {
                ldsm4(qh[kc], a_addr(sm_u,        lane, wm, kc * 2));
                ldsm4(ql[kc], a_addr(sm_u + 8192, lane, wm, kc * 2));
            }
            #pragma unroll
            for (int ct = 0; ct < 8; ct++)
                #pragma unroll
                for (int c = 0; c < 4; c++) o[ct][c] = 0.f;
        }

        for (int j = 0; j <= qtile; j++) {
            const int s = j & 1;

            if (!consumer) {
                // fill next buffer while consumers compute current
                if (j < qtile) {
                    const int n0n = (j + 1) * 64;
                    char* kbase = sm + 16384 + ((j + 1) & 1) * 32768;
                    #pragma unroll
                    for (int i = 0; i < 8; i++) {
                        int f = ptid + i * 128;
                        int row = f >> 4, q4 = f & 15;
                        float4 kv4 = *(const float4*)(kb + (size_t)(n0n + row) * HS + q4 * 4);
                        float4 vv4 = *(const float4*)(vb + (size_t)(n0n + row) * HS + q4 * 4);
                        split_store(kbase,         kbase + 8192,  row, q4, kv4);
                        split_store(kbase + 16384, kbase + 24576, row, q4, vv4);
                    }
                }
            } else {
                const uint32_t kbu = sm_u + 16384 + s * 32768;
                const uint32_t Khi_u = kbu, Klo_u = kbu + 8192;
                const uint32_t Vhi_u = kbu + 16384, Vlo_u = kbu + 24576;

                // ---- S = Q K^T : 16 rows x 64 cols per warp ----
                float sa[8][4];
                #pragma unroll
                for (int nt = 0; nt < 8; nt++)
                    #pragma unroll
                    for (int c = 0; c < 4; c++) sa[nt][c] = 0.f;

                #pragma unroll
                for (int kc = 0; kc < 4; kc++) {
                    #pragma unroll
                    for (int ntp = 0; ntp < 4; ntp++) {
                        uint32_t kh[4], kl4[4];
                        ldsm4(kh,  bk_addr(Khi_u, lane, 16 * ntp, kc * 2));
                        ldsm4(kl4, bk_addr(Klo_u, lane, 16 * ntp, kc * 2));
                        #pragma unroll
                        for (int i = 0; i < 2; i++) {
                            int nt = 2 * ntp + i;
                            mma16816(sa[nt], qh[kc], &kh[2 * i]);
                            mma16816(sa[nt], qh[kc], &kl4[2 * i]);
                            mma16816(sa[nt], ql[kc], &kh[2 * i]);
                        }
                    }
                }

                // ---- scale + causal mask ----
                if (j == qtile) {
                    #pragma unroll
                    for (int nt = 0; nt < 8; nt++) {
                        int c0 = nt * 8 + 2 * tg;
                        sa[nt][0] = (c0     <= wm + g)     ? sa[nt][0] * SCALE : -1e30f;
                        sa[nt][1] = (c0 + 1 <= wm + g)     ? sa[nt][1] * SCALE : -1e30f;
                        sa[nt][2] = (c0     <= wm + g + 8) ? sa[nt][2] * SCALE : -1e30f;
                        sa[nt][3] = (c0 + 1 <= wm + g + 8) ? sa[nt][3] * SCALE : -1e30f;
                    }
                } else {
                    #pragma unroll
                    for (int nt = 0; nt < 8; nt++)
                        #pragma unroll
                        for (int c = 0; c < 4; c++) sa[nt][c] *= SCALE;
                }

                // ---- fragment-resident online softmax ----
                float tm0 = -1e30f, tm1 = -1e30f;
                #pragma unroll
                for (int nt = 0; nt < 8; nt++) {
                    tm0 = fmaxf(tm0, fmaxf(sa[nt][0], sa[nt][1]));
                    tm1 = fmaxf(tm1, fmaxf(sa[nt][2], sa[nt][3]));
                }
                tm0 = fmaxf(tm0, __shfl_xor_sync(0xffffffffu, tm0, 1));
                tm0 = fmaxf(tm0, __shfl_xor_sync(0xffffffffu, tm0, 2));
                tm1 = fmaxf(tm1, __shfl_xor_sync(0xffffffffu, tm1, 1));
                tm1 = fmaxf(tm1, __shfl_xor_sync(0xffffffffu, tm1, 2));
                float mn0 = fmaxf(mr0, tm0), mn1 = fmaxf(mr1, tm1);
                float al0 = __expf(mr0 - mn0), al1 = __expf(mr1 - mn1);
                mr0 = mn0; mr1 = mn1;
                float rs0 = 0.f, rs1 = 0.f;
                #pragma unroll
                for (int nt = 0; nt < 8; nt++) {
                    sa[nt][0] = __expf(sa[nt][0] - mn0);
                    sa[nt][1] = __expf(sa[nt][1] - mn0);
                    sa[nt][2] = __expf(sa[nt][2] - mn1);
                    sa[nt][3] = __expf(sa[nt][3] - mn1);
                    rs0 += sa[nt][0] + sa[nt][1];
                    rs1 += sa[nt][2] + sa[nt][3];
                }
                rs0 += __shfl_xor_sync(0xffffffffu, rs0, 1);
                rs0 += __shfl_xor_sync(0xffffffffu, rs0, 2);
                rs1 += __shfl_xor_sync(0xffffffffu, rs1, 1);
                rs1 += __shfl_xor_sync(0xffffffffu, rs1, 2);
                lr0 = lr0 * al0 + rs0;
                lr1 = lr1 * al1 + rs1;
                #pragma unroll
                for (int ct = 0; ct < 8; ct++) {
                    o[ct][0] *= al0; o[ct][1] *= al0;
                    o[ct][2] *= al1; o[ct][3] *= al1;
                }

                // ---- O += P V ; P repacked accum->A-frags in registers ----
                #pragma unroll
                for (int kp = 0; kp < 2; kp++) {      // 32-key groups
                    uint32_t ph[2][4], pl[2][4];
                    #pragma unroll
                    for (int i = 0; i < 2; i++) {     // k16 halves
                        int t0 = 4 * kp + 2 * i;
                        ph[i][0] = pk2(sa[t0][0], sa[t0][1]);
                        ph[i][1] = pk2(sa[t0][2], sa[t0][3]);
                        ph[i][2] = pk2(sa[t0 + 1][0], sa[t0 + 1][1]);
                        ph[i][3] = pk2(sa[t0 + 1][2], sa[t0 + 1][3]);
                        pl[i][0] = pk2(sa[t0][0] - bhi(sa[t0][0]), sa[t0][1] - bhi(sa[t0][1]));
                        pl[i][1] = pk2(sa[t0][2] - bhi(sa[t0][2]), sa[t0][3] - bhi(sa[t0][3]));
                        pl[i][2] = pk2(sa[t0 + 1][0] - bhi(sa[t0 + 1][0]), sa[t0 + 1][1] - bhi(sa[t0 + 1][1]));
                        pl[i][3] = pk2(sa[t0 + 1][2] - bhi(sa[t0 + 1][2]), sa[t0 + 1][3] - bhi(sa[t0 + 1][3]));
                    }
                    #pragma unroll
                    for (int ct = 0; ct < 8; ct++) {
                        uint32_t vh[4], vl[4];
                        ldsm4t(vh, bv_addr(Vhi_u, lane, kp * 32, ct));
                        ldsm4t(vl, bv_addr(Vlo_u, lane, kp * 32, ct));
                        #pragma unroll
                        for (int i = 0; i < 2; i++) {
                            mma16816(o[ct], ph[i], &vh[2 * i]);
                            mma16816(o[ct], ph[i], &vl[2 * i]);
                            mma16816(o[ct], pl[i], &vh[2 * i]);
                        }
                    }
                }
            }
            __syncthreads();
        }

        // ---- epilogue ----
        if (consumer) {
            float inv0 = 1.0f / lr0, inv1 = 1.0f / lr1;
            #pragma unroll
            for (int ct = 0; ct < 8; ct++) {
                int col = ct * 8 + 2 * tg;
                float2 o0 = make_float2(o[ct][0] * inv0, o[ct][1] * inv0);
                float2 o1 = make_float2(o[ct][2] * inv1, o[ct][3] * inv1);
                *(float2*)(ob + (size_t)(m0 + wm + g)     * HS + col) = o0;
                *(float2*)(ob + (size_t)(m0 + wm + g + 8) * HS + col) = o1;
            }
        }
    }
}

// ---------------------------------------------------------------------------
extern "C" void kernel_launch(void* const* d_in, const int* in_sizes, int n_in,
                              void* d_out, int out_size)
{
    const float* x  = (const float*)d_in[0];
    const float* Wq = (const float*)d_in[1];
    const float* bq = (const float*)d_in[2];
    const float* Wk = (const float*)d_in[3];
    const float* bk = (const float*)d_in[4];
    const float* Wv = (const float*)d_in[5];
    const float* bv = (const float*)d_in[6];
    float* out = (float*)d_out;

    (void)cudaFuncSetAttribute(qkv_mma,
                               cudaFuncAttributeMaxDynamicSharedMemorySize,
                               QKV_SMEM_BYTES);
    (void)cudaFuncSetAttribute(attn_mma,
                               cudaFuncAttributeMaxDynamicSharedMemorySize,
                               ATTN_SMEM_BYTES);

    qkv_mma<<<(BB * TT) / 128, 256, QKV_SMEM_BYTES>>>(x, Wq, bq, Wk, bk, Wv, bv);
    attn_mma<<<dim3(TT / 64 / 2, BB), 256, ATTN_SMEM_BYTES>>>(out);
}